// round 1
// baseline (speedup 1.0000x reference)
#include <cuda_runtime.h>
#include <math.h>
#include <stdint.h>

#define NLEV 16
#define TSIZE (1u << 19)

struct Meta {
    float scale[NLEV];
    int   res[NLEV];
    unsigned hashed;   // bit l set => hashed level (res^3 > T)
};

// ---------- packed f32x2 helpers (Blackwell FFMA2 path) ----------
__device__ __forceinline__ unsigned long long dup2(float v) {
    unsigned long long r; unsigned u = __float_as_uint(v);
    asm("mov.b64 %0, {%1, %1};" : "=l"(r) : "r"(u));
    return r;
}
__device__ __forceinline__ unsigned long long fma2(unsigned long long a,
                                                   unsigned long long b,
                                                   unsigned long long c) {
    unsigned long long d;
    asm("fma.rn.f32x2 %0, %1, %2, %3;" : "=l"(d) : "l"(a), "l"(b), "l"(c));
    return d;
}
__device__ __forceinline__ void unpk(unsigned long long v, float& lo, float& hi) {
    unsigned a, b;
    asm("mov.b64 {%0, %1}, %2;" : "=r"(a), "=r"(b) : "l"(v));
    lo = __uint_as_float(a); hi = __uint_as_float(b);
}
__device__ __forceinline__ unsigned long long packf(float lo, float hi) {
    return ((unsigned long long)__float_as_uint(hi) << 32) |
            (unsigned long long)__float_as_uint(lo);
}

// softplus(10x)/10, stable logaddexp form (matches jax.nn.softplus)
__device__ __forceinline__ float softplus10(float x) {
    float y = 10.0f * x;
    return (fmaxf(y, 0.0f) + log1pf(__expf(-fabsf(y)))) * 0.1f;
}

// Dense layer: out[64] = act[IN] @ W^T using packed f32x2 FMAs.
// w layout: [IN/2][32] ulonglong2; entry (k2, p):
//   .x = pack(W[2p][2k2],   W[2p+1][2k2])
//   .y = pack(W[2p][2k2+1], W[2p+1][2k2+1])
template<int IN>
__device__ __forceinline__ void dense64(const float (&act)[IN],
                                        const ulonglong2* __restrict__ w,
                                        float (&out)[64]) {
    unsigned long long acc[32];
    #pragma unroll
    for (int p = 0; p < 32; p++) acc[p] = 0ull;
    #pragma unroll
    for (int k2 = 0; k2 < IN / 2; k2++) {
        unsigned long long a0 = dup2(act[2 * k2 + 0]);
        unsigned long long a1 = dup2(act[2 * k2 + 1]);
        const ulonglong2* wr = w + k2 * 32;
        #pragma unroll
        for (int p = 0; p < 32; p++) {
            ulonglong2 wv = wr[p];
            acc[p] = fma2(a0, wv.x, acc[p]);
            acc[p] = fma2(a1, wv.y, acc[p]);
        }
    }
    #pragma unroll
    for (int p = 0; p < 32; p++) unpk(acc[p], out[2 * p], out[2 * p + 1]);
}

__global__ void __launch_bounds__(128)
sdf_kernel(const float* __restrict__ x,
           const float* __restrict__ grid,
           const float* __restrict__ W1,
           const float* __restrict__ W2,
           const float* __restrict__ W3,
           const float* __restrict__ W4,
           float* __restrict__ out,
           int N, Meta meta) {
    // ---- stage pair-packed weights in shared ----
    __shared__ ulonglong2 sW1[16 * 32];   //  8 KB
    __shared__ ulonglong2 sW2[32 * 32];   // 16 KB
    __shared__ ulonglong2 sW3[32 * 32];   // 16 KB
    __shared__ float      sW4[64];

    const int tid = threadIdx.x;
    for (int t = tid; t < 16 * 32; t += blockDim.x) {
        int k2 = t >> 5, p = t & 31;
        int j0 = 2 * p, j1 = 2 * p + 1;
        int k0 = 2 * k2, k1 = 2 * k2 + 1;
        sW1[t] = make_ulonglong2(packf(W1[j0 * 32 + k0], W1[j1 * 32 + k0]),
                                 packf(W1[j0 * 32 + k1], W1[j1 * 32 + k1]));
    }
    for (int t = tid; t < 32 * 32; t += blockDim.x) {
        int k2 = t >> 5, p = t & 31;
        int j0 = 2 * p, j1 = 2 * p + 1;
        int k0 = 2 * k2, k1 = 2 * k2 + 1;
        sW2[t] = make_ulonglong2(packf(W2[j0 * 64 + k0], W2[j1 * 64 + k0]),
                                 packf(W2[j0 * 64 + k1], W2[j1 * 64 + k1]));
        sW3[t] = make_ulonglong2(packf(W3[j0 * 64 + k0], W3[j1 * 64 + k0]),
                                 packf(W3[j0 * 64 + k1], W3[j1 * 64 + k1]));
    }
    for (int t = tid; t < 64; t += blockDim.x) sW4[t] = W4[t];
    __syncthreads();

    const int i = blockIdx.x * blockDim.x + tid;
    if (i >= N) return;

    const float px = x[3 * i + 0];
    const float py = x[3 * i + 1];
    const float pz = x[3 * i + 2];

    // ---- hash-grid encoding: 16 levels x 2 features ----
    float enc[32];
    const float2* __restrict__ g2 = (const float2*)grid;

    #pragma unroll
    for (int l = 0; l < NLEV; l++) {
        const float s  = meta.scale[l];
        const int  res = meta.res[l];
        const bool hashed = (meta.hashed >> l) & 1u;

        float fx = fmaf(px, s, 0.5f);
        float fy = fmaf(py, s, 0.5f);
        float fz = fmaf(pz, s, 0.5f);
        float flx = floorf(fx), fly = floorf(fy), flz = floorf(fz);
        float rx = fx - flx, ry = fy - fly, rz = fz - flz;
        int gx = (int)flx, gy = (int)fly, gz = (int)flz;

        float wx[2] = {1.0f - rx, rx};
        float wy[2] = {1.0f - ry, ry};
        float wz[2] = {1.0f - rz, rz};

        float s0 = 0.0f, s1 = 0.0f;
        #pragma unroll
        for (int c = 0; c < 8; c++) {
            const int cx = c & 1, cy = (c >> 1) & 1, cz = (c >> 2) & 1;
            unsigned idx;
            if (hashed) {
                unsigned ux = (unsigned)(gx + cx);
                unsigned uy = (unsigned)(gy + cy);
                unsigned uz = (unsigned)(gz + cz);
                idx = (ux * 1u) ^ (uy * 2654435761u) ^ (uz * 805459861u);
                idx &= (TSIZE - 1u);
            } else {
                int ix = min(max(gx + cx, 0), res - 1);
                int iy = min(max(gy + cy, 0), res - 1);
                int iz = min(max(gz + cz, 0), res - 1);
                idx = (unsigned)(ix + res * (iy + res * iz));
            }
            float2 f = __ldg(&g2[(size_t)l * TSIZE + idx]);
            float w = wx[cx] * wy[cy] * wz[cz];
            s0 = fmaf(w, f.x, s0);
            s1 = fmaf(w, f.y, s1);
        }
        enc[2 * l + 0] = s0;
        enc[2 * l + 1] = s1;
    }

    // ---- MLP 32 -> 64 -> 64 -> 64 -> 1 ----
    float h1[64];
    dense64<32>(enc, sW1, h1);
    #pragma unroll
    for (int j = 0; j < 64; j++) h1[j] = softplus10(h1[j]);

    float h2[64];
    dense64<64>(h1, sW2, h2);
    #pragma unroll
    for (int j = 0; j < 64; j++) h2[j] = softplus10(h2[j]);

    float h3[64];
    dense64<64>(h2, sW3, h3);
    #pragma unroll
    for (int j = 0; j < 64; j++) h3[j] = softplus10(h3[j]);

    float sdf = 0.0f;
    #pragma unroll
    for (int k = 0; k < 64; k++) sdf = fmaf(h3[k], sW4[k], sdf);

    out[i] = sdf;
}

static Meta build_meta() {
    Meta m;
    m.hashed = 0u;
    const double b = pow(2.0, log2(2048.0 / 16.0) / 15.0);
    for (int l = 0; l < NLEV; l++) {
        double sc = 16.0 * pow(b, (double)l) - 1.0;
        int r = (int)ceil(sc) + 1;
        m.scale[l] = (float)sc;
        m.res[l] = r;
        long long r3 = (long long)r * r * r;
        if (r3 > (long long)TSIZE) m.hashed |= (1u << l);
    }
    return m;
}

extern "C" void kernel_launch(void* const* d_in, const int* in_sizes, int n_in,
                              void* d_out, int out_size) {
    const float* x    = (const float*)d_in[0];
    const float* grid = (const float*)d_in[1];
    const float* W1   = (const float*)d_in[2];
    const float* W2   = (const float*)d_in[3];
    const float* W3   = (const float*)d_in[4];
    const float* W4   = (const float*)d_in[5];
    float* out = (float*)d_out;

    const int N = in_sizes[0] / 3;
    Meta meta = build_meta();

    const int threads = 128;
    const int blocks = (N + threads - 1) / threads;
    sdf_kernel<<<blocks, threads>>>(x, grid, W1, W2, W3, W4, out, N, meta);
}